// round 3
// baseline (speedup 1.0000x reference)
#include <cuda_runtime.h>

// cosine_regularizer: out = (sum(W) - N)/N^2 with W = p p^T, p = row-normalized points.
// Identity: sum(W) = || sum_i p_i ||^2  -> single streaming pass + fused scalar finalize.
// R3: ROWS_PER_WARP 4->2 (loads fit regs, batch fully), grid 512->1024 (occ 38%->~80%).

constexpr int N_ROWS = 16384;
constexpr int D      = 256;
constexpr int TPB    = 256;                 // 8 warps
constexpr int WARPS  = TPB / 32;
constexpr int NBLK   = 1024;                // 1024*8 warps * 2 rows = 16384 rows
constexpr int ROWS_PER_WARP = N_ROWS / (NBLK * WARPS);  // 2

__device__ float        g_s[D];       // zero at load; reset by last block each run
__device__ unsigned int g_count;      // zero at load; reset by last block each run

__global__ void __launch_bounds__(TPB)
k_fused(const float* __restrict__ pts, float* __restrict__ out) {
    const int warp  = threadIdx.x >> 5;
    const int lane  = threadIdx.x & 31;
    const int t     = threadIdx.x;
    const int gwarp = blockIdx.x * WARPS + warp;

    // Issue all loads for this warp's 2 rows up front (4 LDG.128 -> 16 regs, batches fully).
    float4 v0[ROWS_PER_WARP], v1[ROWS_PER_WARP];
#pragma unroll
    for (int k = 0; k < ROWS_PER_WARP; k++) {
        const int row = gwarp + k * (NBLK * WARPS);
        const float4* p = reinterpret_cast<const float4*>(pts) + (size_t)row * (D / 4);
        v0[k] = p[lane];        // cols 4*lane   .. 4*lane+3
        v1[k] = p[32 + lane];   // cols 128+4*lane .. +3
    }

    // Per-row sum of squares, warp-wide reduction (chains interleaved).
    float ss[ROWS_PER_WARP];
#pragma unroll
    for (int k = 0; k < ROWS_PER_WARP; k++) {
        ss[k] = v0[k].x * v0[k].x + v0[k].y * v0[k].y + v0[k].z * v0[k].z + v0[k].w * v0[k].w
              + v1[k].x * v1[k].x + v1[k].y * v1[k].y + v1[k].z * v1[k].z + v1[k].w * v1[k].w;
    }
#pragma unroll
    for (int off = 16; off > 0; off >>= 1) {
#pragma unroll
        for (int k = 0; k < ROWS_PER_WARP; k++)
            ss[k] += __shfl_xor_sync(0xffffffffu, ss[k], off);
    }

    // rnorm * row accumulated into per-lane column accumulators.
    float4 a0 = make_float4(0.f, 0.f, 0.f, 0.f);
    float4 a1 = make_float4(0.f, 0.f, 0.f, 0.f);
#pragma unroll
    for (int k = 0; k < ROWS_PER_WARP; k++) {
        const float rn = rsqrtf(ss[k]);
        a0.x += rn * v0[k].x;  a0.y += rn * v0[k].y;
        a0.z += rn * v0[k].z;  a0.w += rn * v0[k].w;
        a1.x += rn * v1[k].x;  a1.y += rn * v1[k].y;
        a1.z += rn * v1[k].z;  a1.w += rn * v1[k].w;
    }

    // Block-reduce 8 warps' column partials, one atomic per column per block.
    __shared__ float sh[WARPS][D];
    float4* shv = reinterpret_cast<float4*>(sh[warp]);
    shv[lane]      = a0;
    shv[32 + lane] = a1;
    __syncthreads();

    float s = sh[0][t];
#pragma unroll
    for (int w = 1; w < WARPS; w++) s += sh[w][t];
    atomicAdd(&g_s[t], s);

    // ---- last-block-done finalize ----
    __shared__ unsigned int s_isLast;
    __threadfence();                       // make our g_s adds visible before the count
    __syncthreads();                       // all threads' atomics issued before counting
    if (t == 0) {
        const unsigned int old = atomicAdd(&g_count, 1u);
        s_isLast = (old == (unsigned int)(NBLK - 1)) ? 1u : 0u;
    }
    __syncthreads();
    if (!s_isLast) return;

    // Last block: all other blocks' g_s contributions are L2-visible.
    const float v = __ldcg(&g_s[t]);       // L2 read, bypass (possibly stale) L1
    g_s[t] = 0.0f;                         // reset for next graph replay
    if (t == 0) g_count = 0u;

    double d = (double)v * (double)v;
#pragma unroll
    for (int off = 16; off > 0; off >>= 1)
        d += __shfl_xor_sync(0xffffffffu, d, off);

    __shared__ double wsum[WARPS];
    if (lane == 0) wsum[warp] = d;
    __syncthreads();
    if (warp == 0) {
        double x = (lane < WARPS) ? wsum[lane] : 0.0;
#pragma unroll
        for (int off = 4; off > 0; off >>= 1)
            x += __shfl_xor_sync(0xffffffffu, x, off);
        if (lane == 0) {
            const double n = (double)N_ROWS;
            out[0] = (float)((x - n) / (n * n));
        }
    }
}

extern "C" void kernel_launch(void* const* d_in, const int* in_sizes, int n_in,
                              void* d_out, int out_size) {
    const float* pts = (const float*)d_in[0];
    (void)in_sizes; (void)n_in; (void)out_size;
    k_fused<<<NBLK, TPB>>>(pts, (float*)d_out);
}

// round 4
// speedup vs baseline: 1.1358x; 1.1358x over previous
#include <cuda_runtime.h>

// cosine_regularizer: out = (sum(W) - N)/N^2, W = p p^T, p = row-normalized points.
// Identity: sum(W) = || sum_i p_i ||^2  -> one streaming pass + scalar finalize.
// R4: 148 CTAs x 1024 thr (one wave, one CTA/SM). Epilogue atomics 148 blocks only
//     (R2/R3 showed epilogue cost scales with block count: contended g_s atomics + fence).

constexpr int N_ROWS = 16384;
constexpr int D      = 256;
constexpr int NBLK   = 148;
constexpr int TPB    = 1024;               // 32 warps
constexpr int WARPS  = TPB / 32;
constexpr int TOTW   = NBLK * WARPS;       // 4736 warps; 16384/4736 = 3..4 rows/warp

__device__ float        g_s[D];       // zero at load; reset by last block each run
__device__ unsigned int g_count;      // zero at load; reset by last block each run

__global__ void __launch_bounds__(TPB, 1)
k_fused(const float* __restrict__ pts, float* __restrict__ out) {
    const int warp = threadIdx.x >> 5;
    const int lane = threadIdx.x & 31;
    const int t    = threadIdx.x;
    const int gw   = blockIdx.x * WARPS + warp;      // 0..4735

    __shared__ float bs[D];            // block-level column accumulator
    if (t < D) bs[t] = 0.0f;
    __syncthreads();

    // Rows gw + k*TOTW, k=0..2 always valid; k=3 only if gw < 16384 - 3*4736.
    const bool has4 = (gw + 3 * TOTW) < N_ROWS;

    // Batch-issue all loads (6 or 8 LDG.128 per lane in flight).
    float4 v0[4], v1[4];
#pragma unroll
    for (int k = 0; k < 3; k++) {
        const float4* p = reinterpret_cast<const float4*>(pts)
                        + (size_t)(gw + k * TOTW) * (D / 4);
        v0[k] = p[lane];
        v1[k] = p[32 + lane];
    }
    {
        const int r3 = has4 ? (gw + 3 * TOTW) : gw;   // safe addr; zeroed below
        const float4* p = reinterpret_cast<const float4*>(pts) + (size_t)r3 * (D / 4);
        v0[3] = p[lane];
        v1[3] = p[32 + lane];
    }

    // Per-row sum of squares, 4 interleaved warp reductions.
    float ss[4];
#pragma unroll
    for (int k = 0; k < 4; k++) {
        ss[k] = v0[k].x * v0[k].x + v0[k].y * v0[k].y + v0[k].z * v0[k].z + v0[k].w * v0[k].w
              + v1[k].x * v1[k].x + v1[k].y * v1[k].y + v1[k].z * v1[k].z + v1[k].w * v1[k].w;
    }
#pragma unroll
    for (int off = 16; off > 0; off >>= 1) {
#pragma unroll
        for (int k = 0; k < 4; k++)
            ss[k] += __shfl_xor_sync(0xffffffffu, ss[k], off);
    }

    // Accumulate rnorm * row (4th row contributes 0 when absent).
    float4 a0 = make_float4(0.f, 0.f, 0.f, 0.f);
    float4 a1 = make_float4(0.f, 0.f, 0.f, 0.f);
#pragma unroll
    for (int k = 0; k < 4; k++) {
        const float rn = (k < 3 || has4) ? rsqrtf(ss[k]) : 0.0f;
        a0.x += rn * v0[k].x;  a0.y += rn * v0[k].y;
        a0.z += rn * v0[k].z;  a0.w += rn * v0[k].w;
        a1.x += rn * v1[k].x;  a1.y += rn * v1[k].y;
        a1.z += rn * v1[k].z;  a1.w += rn * v1[k].w;
    }

    // Warp partials -> block accumulator via shared atomics (lane-spread, conflict-free).
    atomicAdd(&bs[4 * lane + 0], a0.x);
    atomicAdd(&bs[4 * lane + 1], a0.y);
    atomicAdd(&bs[4 * lane + 2], a0.z);
    atomicAdd(&bs[4 * lane + 3], a0.w);
    atomicAdd(&bs[128 + 4 * lane + 0], a1.x);
    atomicAdd(&bs[128 + 4 * lane + 1], a1.y);
    atomicAdd(&bs[128 + 4 * lane + 2], a1.z);
    atomicAdd(&bs[128 + 4 * lane + 3], a1.w);
    __syncthreads();

    // One global atomic round per block (148 adds per address chip-wide).
    if (t < D) atomicAdd(&g_s[t], bs[t]);

    // ---- last-block-done finalize ----
    __shared__ unsigned int s_isLast;
    __threadfence();
    __syncthreads();
    if (t == 0) {
        const unsigned int old = atomicAdd(&g_count, 1u);
        s_isLast = (old == (unsigned int)(NBLK - 1)) ? 1u : 0u;
    }
    __syncthreads();
    if (!s_isLast) return;

    double d = 0.0;
    if (t < D) {
        const float v = __ldcg(&g_s[t]);   // L2 read (L1 may be stale)
        g_s[t] = 0.0f;                     // reset for next graph replay
        d = (double)v * (double)v;
    }
    if (t == 0) g_count = 0u;

#pragma unroll
    for (int off = 16; off > 0; off >>= 1)
        d += __shfl_xor_sync(0xffffffffu, d, off);

    __shared__ double wsum[WARPS];
    if (lane == 0) wsum[warp] = d;
    __syncthreads();
    if (warp == 0) {
        double x = (lane < WARPS) ? wsum[lane] : 0.0;
#pragma unroll
        for (int off = 16; off > 0; off >>= 1)
            x += __shfl_xor_sync(0xffffffffu, x, off);
        if (lane == 0) {
            const double n = (double)N_ROWS;
            out[0] = (float)((x - n) / (n * n));
        }
    }
}

extern "C" void kernel_launch(void* const* d_in, const int* in_sizes, int n_in,
                              void* d_out, int out_size) {
    const float* pts = (const float*)d_in[0];
    (void)in_sizes; (void)n_in; (void)out_size;
    k_fused<<<NBLK, TPB>>>(pts, (float*)d_out);
}

// round 5
// speedup vs baseline: 1.3208x; 1.1629x over previous
#include <cuda_runtime.h>

// cosine_regularizer: out = (sum(W) - N)/N^2, W = p p^T, p = row-normalized points.
// Identity: sum(W) = || sum_i p_i ||^2  -> one streaming pass + scalar finalize.
// R5: R1's streaming shape (512x256, 4 rows/warp — fastest observed) + cheap epilogue:
//     relaxed REDs + release/acquire counter instead of __threadfence (full MEMBAR.GPU).

constexpr int N_ROWS = 16384;
constexpr int D      = 256;
constexpr int TPB    = 256;                 // 8 warps
constexpr int WARPS  = TPB / 32;
constexpr int NBLK   = 512;                 // 512*8 warps * 4 rows = 16384 rows
constexpr int ROWS_PER_WARP = 4;

__device__ float        g_s[D];       // zero at load; reset by last block each run
__device__ unsigned int g_count;      // zero at load; reset by last block each run

__global__ void __launch_bounds__(TPB)
k_fused(const float* __restrict__ pts, float* __restrict__ out) {
    const int warp = threadIdx.x >> 5;
    const int lane = threadIdx.x & 31;
    const int t    = threadIdx.x;
    const int gw   = blockIdx.x * WARPS + warp;

    // Batch-issue all 8 LDG.128 for this warp's 4 rows.
    float4 v0[ROWS_PER_WARP], v1[ROWS_PER_WARP];
#pragma unroll
    for (int k = 0; k < ROWS_PER_WARP; k++) {
        const int row = gw + k * (NBLK * WARPS);
        const float4* p = reinterpret_cast<const float4*>(pts) + (size_t)row * (D / 4);
        v0[k] = p[lane];        // cols 4*lane   .. +3
        v1[k] = p[32 + lane];   // cols 128+4*lane .. +3
    }

    // Per-row sum of squares; 4 interleaved warp reductions.
    float ss[ROWS_PER_WARP];
#pragma unroll
    for (int k = 0; k < ROWS_PER_WARP; k++) {
        ss[k] = v0[k].x * v0[k].x + v0[k].y * v0[k].y + v0[k].z * v0[k].z + v0[k].w * v0[k].w
              + v1[k].x * v1[k].x + v1[k].y * v1[k].y + v1[k].z * v1[k].z + v1[k].w * v1[k].w;
    }
#pragma unroll
    for (int off = 16; off > 0; off >>= 1) {
#pragma unroll
        for (int k = 0; k < ROWS_PER_WARP; k++)
            ss[k] += __shfl_xor_sync(0xffffffffu, ss[k], off);
    }

    // rnorm * row into per-lane column accumulators.
    float4 a0 = make_float4(0.f, 0.f, 0.f, 0.f);
    float4 a1 = make_float4(0.f, 0.f, 0.f, 0.f);
#pragma unroll
    for (int k = 0; k < ROWS_PER_WARP; k++) {
        const float rn = rsqrtf(ss[k]);
        a0.x += rn * v0[k].x;  a0.y += rn * v0[k].y;
        a0.z += rn * v0[k].z;  a0.w += rn * v0[k].w;
        a1.x += rn * v1[k].x;  a1.y += rn * v1[k].y;
        a1.z += rn * v1[k].z;  a1.w += rn * v1[k].w;
    }

    // Block-reduce 8 warps' column partials via shared.
    __shared__ float sh[WARPS][D];
    float4* shv = reinterpret_cast<float4*>(sh[warp]);
    shv[lane]      = a0;
    shv[32 + lane] = a1;
    __syncthreads();

    float s = sh[0][t];
#pragma unroll
    for (int w = 1; w < WARPS; w++) s += sh[w][t];

    // Relaxed RED per column (result unused -> REDG), no fence.
    atomicAdd(&g_s[t], s);

    // ---- last-block detection with release/acquire (no full MEMBAR) ----
    __shared__ unsigned int s_isLast;
    __syncthreads();   // all REDs of this block happen-before t0's release-atom
    if (t == 0) {
        unsigned int old;
        asm volatile("atom.release.gpu.global.add.u32 %0, [%1], 1;"
                     : "=r"(old) : "l"(&g_count) : "memory");
        s_isLast = (old == (unsigned int)(NBLK - 1)) ? 1u : 0u;
    }
    __syncthreads();
    if (!s_isLast) return;

    // Acquire: pair with all blocks' release-atoms, then L2 reads are coherent.
    if (t == 0) {
        unsigned int dummy;
        asm volatile("atom.acquire.gpu.global.add.u32 %0, [%1], 0;"
                     : "=r"(dummy) : "l"(&g_count) : "memory");
        g_count = 0u;   // reset for next graph replay
    }
    __syncthreads();

    const float v = __ldcg(&g_s[t]);   // L1-bypass read of the final column sums
    g_s[t] = 0.0f;                     // reset for next graph replay

    double d = (double)v * (double)v;
#pragma unroll
    for (int off = 16; off > 0; off >>= 1)
        d += __shfl_xor_sync(0xffffffffu, d, off);

    __shared__ double wsum[WARPS];
    if (lane == 0) wsum[warp] = d;
    __syncthreads();
    if (warp == 0) {
        double x = (lane < WARPS) ? wsum[lane] : 0.0;
#pragma unroll
        for (int off = 4; off > 0; off >>= 1)
            x += __shfl_xor_sync(0xffffffffu, x, off);
        if (lane == 0) {
            const double n = (double)N_ROWS;
            out[0] = (float)((x - n) / (n * n));
        }
    }
}

extern "C" void kernel_launch(void* const* d_in, const int* in_sizes, int n_in,
                              void* d_out, int out_size) {
    const float* pts = (const float*)d_in[0];
    (void)in_sizes; (void)n_in; (void)out_size;
    k_fused<<<NBLK, TPB>>>(pts, (float*)d_out);
}

// round 6
// speedup vs baseline: 1.9375x; 1.4669x over previous
#include <cuda_runtime.h>

// cosine_regularizer: out = (sum(W) - N)/N^2, W = p p^T, p = row-normalized points.
// Identity: sum(W) = || sum_i p_i ||^2  -> one streaming pass + scalar finalize.
// R6: 16 replicas of the column-sum vector. 512 blocks / 16 replicas = 32 atomic
//     adds per address (vs 512) -> per-address L2 atomic drain off the critical path.

constexpr int N_ROWS = 16384;
constexpr int D      = 256;
constexpr int TPB    = 256;                 // 8 warps
constexpr int WARPS  = TPB / 32;
constexpr int NBLK   = 512;                 // 512*8 warps * 4 rows = 16384 rows
constexpr int ROWS_PER_WARP = 4;
constexpr int NREP   = 16;                  // replica count (power of 2)

__device__ float        g_rep[NREP][D];   // zero at load; reset by last block each run
__device__ unsigned int g_count;          // zero at load; reset by last block each run

__global__ void __launch_bounds__(TPB)
k_fused(const float* __restrict__ pts, float* __restrict__ out) {
    const int warp = threadIdx.x >> 5;
    const int lane = threadIdx.x & 31;
    const int t    = threadIdx.x;
    const int gw   = blockIdx.x * WARPS + warp;

    // Batch-issue all 8 LDG.128 for this warp's 4 rows.
    float4 v0[ROWS_PER_WARP], v1[ROWS_PER_WARP];
#pragma unroll
    for (int k = 0; k < ROWS_PER_WARP; k++) {
        const int row = gw + k * (NBLK * WARPS);
        const float4* p = reinterpret_cast<const float4*>(pts) + (size_t)row * (D / 4);
        v0[k] = p[lane];        // cols 4*lane   .. +3
        v1[k] = p[32 + lane];   // cols 128+4*lane .. +3
    }

    // Per-row sum of squares; 4 interleaved warp reductions.
    float ss[ROWS_PER_WARP];
#pragma unroll
    for (int k = 0; k < ROWS_PER_WARP; k++) {
        ss[k] = v0[k].x * v0[k].x + v0[k].y * v0[k].y + v0[k].z * v0[k].z + v0[k].w * v0[k].w
              + v1[k].x * v1[k].x + v1[k].y * v1[k].y + v1[k].z * v1[k].z + v1[k].w * v1[k].w;
    }
#pragma unroll
    for (int off = 16; off > 0; off >>= 1) {
#pragma unroll
        for (int k = 0; k < ROWS_PER_WARP; k++)
            ss[k] += __shfl_xor_sync(0xffffffffu, ss[k], off);
    }

    // rnorm * row into per-lane column accumulators.
    float4 a0 = make_float4(0.f, 0.f, 0.f, 0.f);
    float4 a1 = make_float4(0.f, 0.f, 0.f, 0.f);
#pragma unroll
    for (int k = 0; k < ROWS_PER_WARP; k++) {
        const float rn = rsqrtf(ss[k]);
        a0.x += rn * v0[k].x;  a0.y += rn * v0[k].y;
        a0.z += rn * v0[k].z;  a0.w += rn * v0[k].w;
        a1.x += rn * v1[k].x;  a1.y += rn * v1[k].y;
        a1.z += rn * v1[k].z;  a1.w += rn * v1[k].w;
    }

    // Block-reduce 8 warps' column partials via shared.
    __shared__ float sh[WARPS][D];
    float4* shv = reinterpret_cast<float4*>(sh[warp]);
    shv[lane]      = a0;
    shv[32 + lane] = a1;
    __syncthreads();

    float s = sh[0][t];
#pragma unroll
    for (int w = 1; w < WARPS; w++) s += sh[w][t];

    // Per-column add into this block's replica (32 adds/address chip-wide).
    atomicAdd(&g_rep[blockIdx.x & (NREP - 1)][t], s);

    // ---- last-block detection (release/acquire) ----
    __shared__ unsigned int s_isLast;
    __syncthreads();   // block's adds happen-before t0's release-atom
    if (t == 0) {
        unsigned int old;
        asm volatile("atom.release.gpu.global.add.u32 %0, [%1], 1;"
                     : "=r"(old) : "l"(&g_count) : "memory");
        s_isLast = (old == (unsigned int)(NBLK - 1)) ? 1u : 0u;
    }
    __syncthreads();
    if (!s_isLast) return;

    // Acquire: pairs with all blocks' releases; subsequent L2 reads are coherent.
    if (t == 0) {
        unsigned int dummy;
        asm volatile("atom.acquire.gpu.global.add.u32 %0, [%1], 0;"
                     : "=r"(dummy) : "l"(&g_count) : "memory");
        g_count = 0u;   // reset for next graph replay
    }
    __syncthreads();

    // Fold replicas for this column; reset them for next replay.
    float v = 0.0f;
#pragma unroll
    for (int r = 0; r < NREP; r++) {
        v += __ldcg(&g_rep[r][t]);
        g_rep[r][t] = 0.0f;
    }

    double d = (double)v * (double)v;
#pragma unroll
    for (int off = 16; off > 0; off >>= 1)
        d += __shfl_xor_sync(0xffffffffu, d, off);

    __shared__ double wsum[WARPS];
    if (lane == 0) wsum[warp] = d;
    __syncthreads();
    if (warp == 0) {
        double x = (lane < WARPS) ? wsum[lane] : 0.0;
#pragma unroll
        for (int off = 4; off > 0; off >>= 1)
            x += __shfl_xor_sync(0xffffffffu, x, off);
        if (lane == 0) {
            const double n = (double)N_ROWS;
            out[0] = (float)((x - n) / (n * n));
        }
    }
}

extern "C" void kernel_launch(void* const* d_in, const int* in_sizes, int n_in,
                              void* d_out, int out_size) {
    const float* pts = (const float*)d_in[0];
    (void)in_sizes; (void)n_in; (void)out_size;
    k_fused<<<NBLK, TPB>>>(pts, (float*)d_out);
}